// round 11
// baseline (speedup 1.0000x reference)
#include <cuda_runtime.h>
#include <cuda_fp16.h>
#include <stdint.h>
#include <stddef.h>
#include <math.h>

#define SEQ 4096
#define EMB 1024
#define OUTD 1024

// ---------------- scratch (__device__ globals; allocation-free rule) -------
__device__ __half g_Xh[(size_t)SEQ * EMB];
__device__ __half g_WQh[(size_t)OUTD * EMB];
__device__ __half g_WKh[(size_t)OUTD * EMB];
__device__ __half g_WVh[(size_t)OUTD * EMB];
__device__ __half g_Qh[(size_t)SEQ * OUTD];
__device__ __half g_Kh[(size_t)SEQ * OUTD];
__device__ __half g_Vth[(size_t)OUTD * SEQ];          // V^T
__device__ float  g_S[(size_t)SEQ * SEQ];
__device__ __half g_Ph[(size_t)SEQ * SEQ];

// ---------------- PTX helpers ----------------------------------------------
__device__ __forceinline__ uint32_t smem_u32(const void* p) {
    uint32_t a;
    asm("{ .reg .u64 t; cvta.to.shared.u64 t, %1; cvt.u32.u64 %0, t; }"
        : "=r"(a) : "l"(p));
    return a;
}
__device__ __forceinline__ void cp16(uint32_t dst, const void* src) {
    asm volatile("cp.async.cg.shared.global [%0], [%1], 16;" :: "r"(dst), "l"(src));
}
__device__ __forceinline__ void cp_commit() {
    asm volatile("cp.async.commit_group;" ::: "memory");
}
__device__ __forceinline__ void cp_wait2() {
    asm volatile("cp.async.wait_group 2;" ::: "memory");
}
__device__ __forceinline__ void ldsm4(uint32_t& r0, uint32_t& r1, uint32_t& r2,
                                      uint32_t& r3, uint32_t addr) {
    asm volatile("ldmatrix.sync.aligned.m8n8.x4.shared.b16 {%0,%1,%2,%3}, [%4];"
                 : "=r"(r0), "=r"(r1), "=r"(r2), "=r"(r3) : "r"(addr));
}
__device__ __forceinline__ void mma16816(float* c, const uint32_t* a,
                                         const uint32_t* b) {
    asm volatile(
        "mma.sync.aligned.m16n8k16.row.col.f32.f16.f16.f32 "
        "{%0,%1,%2,%3}, {%4,%5,%6,%7}, {%8,%9}, {%0,%1,%2,%3};"
        : "+f"(c[0]), "+f"(c[1]), "+f"(c[2]), "+f"(c[3])
        : "r"(a[0]), "r"(a[1]), "r"(a[2]), "r"(a[3]), "r"(b[0]), "r"(b[1]));
}

// ---------------- plain fp16 warp-MMA GEMM ---------------------------------
// C[M,N] = alpha * A[M,K] @ B[N,K]^T, fp16 A and B, K-major rows.
// CTA 256x128, BK=64, 3 cp.async stages, 16 warps (4M x 4N), warp tile 64x32.
// MODE 0: fp32 C. MODE 1: fp16 C1. MODE 2: fp16 transposed (C*[col][row]).
#define BM 256
#define BN 128
#define BK 64
#define NTHR 512

#define OFF_A 0u
#define OFF_B 32768u
#define STG   49152u
#define GEMM_SMEM (3 * 49152)

template <int MODE>
__global__ void __launch_bounds__(NTHR, 1) gemm_h(
    const __half* __restrict__ A, const __half* __restrict__ B,
    float* __restrict__ Cf, __half* __restrict__ C1,
    int K, int ldc, float alpha)
{
    extern __shared__ char smem_raw[];
    const uint32_t SBASE = smem_u32(smem_raw);

    const int t    = threadIdx.x;
    const int w    = t >> 5;
    const int lane = t & 31;
    const int m0   = blockIdx.y * BM;
    const int n0   = blockIdx.x * BN;
    const int warp_m = (w >> 2) * 64;   // 0..192
    const int warp_n = (w & 3) * 32;    // 0..96

    float acc[4][4][4];
#pragma unroll
    for (int i = 0; i < 4; i++)
#pragma unroll
        for (int j = 0; j < 4; j++)
#pragma unroll
            for (int q = 0; q < 4; q++) acc[i][j][q] = 0.0f;

    // ---- cp.async plan: 6 x 16B chunks per thread per stage ----
    const int trow = t >> 3;             // 0..63
    const int tc8  = t & 7;              // 0..7
    const uint32_t swc = (uint32_t)tc8 * 16;
    const __half* pA = A + (size_t)m0 * K;
    const __half* pB = B + (size_t)n0 * K;

    auto load_stage = [&](int s, int k0) {
        const uint32_t sb = SBASE + (uint32_t)s * STG;
#pragma unroll
        for (int i = 0; i < 6; i++) {
            const bool isA = (i < 4);
            const int row0 = isA ? i * 64 : (i - 4) * 64;
            const __half* base = isA ? pA : pB;
            const uint32_t toff = isA ? OFF_A : OFF_B;
            int rl = row0 + trow;
            const __half* src = base + (size_t)rl * K + tc8 * 8 + k0;
            uint32_t off = toff + (uint32_t)rl * 128 +
                           (swc ^ (((uint32_t)rl & 7) << 4));
            cp16(sb + off, src);
        }
    };

    // ---- ldmatrix address precompute ----
    uint32_t a_off[4], a_xor[4];
#pragma unroll
    for (int mf = 0; mf < 4; mf++) {
        int rl = warp_m + mf * 16 + (lane & 15);
        a_off[mf] = (uint32_t)rl * 128;
        a_xor[mf] = ((uint32_t)rl & 7) << 4;
    }
    const uint32_t a_bc = ((uint32_t)lane >> 4) * 16;
    uint32_t b_off[2], b_xor[2];
#pragma unroll
    for (int nfp = 0; nfp < 2; nfp++) {
        int rl = warp_n + nfp * 16 + (lane & 7) + ((lane & 16) ? 8 : 0);
        b_off[nfp] = (uint32_t)rl * 128;
        b_xor[nfp] = ((uint32_t)rl & 7) << 4;
    }
    const uint32_t b_bc = (((uint32_t)lane >> 3) & 1) * 16;

    const int kt = K / BK;

    // prologue: stages 0,1
    load_stage(0, 0);   cp_commit();
    load_stage(1, BK);  cp_commit();

    for (int it = 0; it < kt; it++) {
        if (it + 2 < kt) load_stage((it + 2) % 3, (it + 2) * BK);
        cp_commit();                       // always (possibly empty group)
        cp_wait2();                        // stage `it` resident
        __syncthreads();

        const uint32_t sb = SBASE + (uint32_t)(it % 3) * STG;

#pragma unroll
        for (int ks = 0; ks < 4; ks++) {
            const uint32_t bcA = (uint32_t)ks * 32 + a_bc;
            const uint32_t bcB = (uint32_t)ks * 32 + b_bc;
            uint32_t bh[4][2];
#pragma unroll
            for (int nfp = 0; nfp < 2; nfp++) {
                uint32_t r0, r1, r2, r3;
                ldsm4(r0, r1, r2, r3, sb + OFF_B + b_off[nfp] + (bcB ^ b_xor[nfp]));
                bh[2 * nfp][0] = r0; bh[2 * nfp][1] = r1;
                bh[2 * nfp + 1][0] = r2; bh[2 * nfp + 1][1] = r3;
            }
#pragma unroll
            for (int mf = 0; mf < 4; mf++) {
                uint32_t ah[4];
                ldsm4(ah[0], ah[1], ah[2], ah[3],
                      sb + OFF_A + a_off[mf] + (bcA ^ a_xor[mf]));
#pragma unroll
                for (int nf = 0; nf < 4; nf++)
                    mma16816(acc[mf][nf], ah, bh[nf]);
            }
        }
        __syncthreads();
    }

    // ---- epilogue ----
#pragma unroll
    for (int mf = 0; mf < 4; mf++) {
#pragma unroll
        for (int nf = 0; nf < 4; nf++) {
            int row = m0 + warp_m + mf * 16 + (lane >> 2);
            int col = n0 + warp_n + nf * 8 + (lane & 3) * 2;
            float f00 = acc[mf][nf][0] * alpha;
            float f01 = acc[mf][nf][1] * alpha;
            float f10 = acc[mf][nf][2] * alpha;
            float f11 = acc[mf][nf][3] * alpha;
            if (MODE == 0) {
                *(float2*)(Cf + (size_t)row * ldc + col)       = make_float2(f00, f01);
                *(float2*)(Cf + (size_t)(row + 8) * ldc + col) = make_float2(f10, f11);
            } else if (MODE == 1) {
                *(__half2*)(C1 + (size_t)row * ldc + col) =
                    __halves2half2(__float2half_rn(f00), __float2half_rn(f01));
                *(__half2*)(C1 + (size_t)(row + 8) * ldc + col) =
                    __halves2half2(__float2half_rn(f10), __float2half_rn(f11));
            } else { // MODE 2: transposed single: C*[col][row], ldc = M_total
                C1[(size_t)col * ldc + row]           = __float2half_rn(f00);
                C1[(size_t)(col + 1) * ldc + row]     = __float2half_rn(f01);
                C1[(size_t)col * ldc + row + 8]       = __float2half_rn(f10);
                C1[(size_t)(col + 1) * ldc + row + 8] = __float2half_rn(f11);
            }
        }
    }
}

// ---------------- fp32 -> fp16 convert --------------------------------------
__global__ void __launch_bounds__(256) conv_half_kernel(
    const float* __restrict__ in, __half* __restrict__ out, int n4)
{
    int i = blockIdx.x * 256 + threadIdx.x;
    if (i >= n4) return;
    float4 v = ((const float4*)in)[i];
    ((__half2*)out)[2 * i]     = __halves2half2(__float2half_rn(v.x), __float2half_rn(v.y));
    ((__half2*)out)[2 * i + 1] = __halves2half2(__float2half_rn(v.z), __float2half_rn(v.w));
}

// ---------------- row softmax -> fp16 Ph ------------------------------------
__global__ void __launch_bounds__(256) softmax_h_kernel(
    const float* __restrict__ S, __half* __restrict__ Ph)
{
    __shared__ float red[8];
    const int row = blockIdx.x;
    const int t   = threadIdx.x;
    const float* p = S + (size_t)row * SEQ;

    float4 v[4];
#pragma unroll
    for (int i = 0; i < 4; i++)
        v[i] = *(const float4*)(p + 4 * (t + 256 * i));

    float mx = -INFINITY;
#pragma unroll
    for (int i = 0; i < 4; i++)
        mx = fmaxf(mx, fmaxf(fmaxf(v[i].x, v[i].y), fmaxf(v[i].z, v[i].w)));
#pragma unroll
    for (int o = 16; o > 0; o >>= 1)
        mx = fmaxf(mx, __shfl_xor_sync(0xFFFFFFFFu, mx, o));
    if ((t & 31) == 0) red[t >> 5] = mx;
    __syncthreads();
    {
        float m = red[t & 7];
#pragma unroll
        for (int o = 4; o > 0; o >>= 1)
            m = fmaxf(m, __shfl_xor_sync(0xFFFFFFFFu, m, o));
        mx = m;
    }
    __syncthreads();

    float sum = 0.0f;
#pragma unroll
    for (int i = 0; i < 4; i++) {
        v[i].x = expf(v[i].x - mx); v[i].y = expf(v[i].y - mx);
        v[i].z = expf(v[i].z - mx); v[i].w = expf(v[i].w - mx);
        sum += v[i].x + v[i].y + v[i].z + v[i].w;
    }
#pragma unroll
    for (int o = 16; o > 0; o >>= 1)
        sum += __shfl_xor_sync(0xFFFFFFFFu, sum, o);
    if ((t & 31) == 0) red[t >> 5] = sum;
    __syncthreads();
    {
        float s2 = red[t & 7];
#pragma unroll
        for (int o = 4; o > 0; o >>= 1)
            s2 += __shfl_xor_sync(0xFFFFFFFFu, s2, o);
        sum = s2;
    }

    const float inv = 1.0f / sum;
#pragma unroll
    for (int i = 0; i < 4; i++) {
        size_t idx = (size_t)row * SEQ + 4 * (t + 256 * i);
        *(__half2*)(Ph + idx) = __halves2half2(
            __float2half_rn(v[i].x * inv), __float2half_rn(v[i].y * inv));
        *(__half2*)(Ph + idx + 2) = __halves2half2(
            __float2half_rn(v[i].z * inv), __float2half_rn(v[i].w * inv));
    }
}

// ---------------------------------------------------------------------------
extern "C" void kernel_launch(void* const* d_in, const int* in_sizes, int n_in,
                              void* d_out, int out_size)
{
    (void)in_sizes; (void)n_in; (void)out_size;
    const float* X  = (const float*)d_in[0];
    const float* WQ = (const float*)d_in[1];
    const float* WK = (const float*)d_in[2];
    const float* WV = (const float*)d_in[3];
    float* O = (float*)d_out;

    __half *Xh, *WQh, *WKh, *WVh, *Qh, *Kh, *Vth, *Ph;
    float* S;
    cudaGetSymbolAddress((void**)&Xh, g_Xh);
    cudaGetSymbolAddress((void**)&WQh, g_WQh);
    cudaGetSymbolAddress((void**)&WKh, g_WKh);
    cudaGetSymbolAddress((void**)&WVh, g_WVh);
    cudaGetSymbolAddress((void**)&Qh, g_Qh);
    cudaGetSymbolAddress((void**)&Kh, g_Kh);
    cudaGetSymbolAddress((void**)&Vth, g_Vth);
    cudaGetSymbolAddress((void**)&Ph, g_Ph);
    cudaGetSymbolAddress((void**)&S, g_S);

    cudaFuncSetAttribute(gemm_h<0>, cudaFuncAttributeMaxDynamicSharedMemorySize, GEMM_SMEM);
    cudaFuncSetAttribute(gemm_h<1>, cudaFuncAttributeMaxDynamicSharedMemorySize, GEMM_SMEM);
    cudaFuncSetAttribute(gemm_h<2>, cudaFuncAttributeMaxDynamicSharedMemorySize, GEMM_SMEM);

    // 1) fp32 -> fp16 conversions
    {
        int n4 = SEQ * EMB / 4;
        conv_half_kernel<<<(n4 + 255) / 256, 256>>>(X, Xh, n4);
        int w4 = OUTD * EMB / 4;
        conv_half_kernel<<<(w4 + 255) / 256, 256>>>(WQ, WQh, w4);
        conv_half_kernel<<<(w4 + 255) / 256, 256>>>(WK, WKh, w4);
        conv_half_kernel<<<(w4 + 255) / 256, 256>>>(WV, WVh, w4);
    }

    dim3 thr(NTHR);

    // 2) projections (NT): Q, K fp16; V fp16 transposed
    dim3 gp(OUTD / BN, SEQ / BM);
    gemm_h<1><<<gp, thr, GEMM_SMEM>>>(Xh, WQh, nullptr, Qh, EMB, OUTD, 1.0f);
    gemm_h<1><<<gp, thr, GEMM_SMEM>>>(Xh, WKh, nullptr, Kh, EMB, OUTD, 1.0f);
    gemm_h<2><<<gp, thr, GEMM_SMEM>>>(Xh, WVh, nullptr, Vth, EMB, SEQ, 1.0f);

    // 3) scores: S = (Q @ K^T) / 32
    dim3 gs(SEQ / BN, SEQ / BM);
    gemm_h<0><<<gs, thr, GEMM_SMEM>>>(Qh, Kh, S, nullptr, OUTD, SEQ, 0.03125f);

    // 4) softmax -> fp16 Ph
    softmax_h_kernel<<<SEQ, 256>>>(S, Ph);

    // 5) O = P @ V (B = V^T)
    dim3 go(OUTD / BN, SEQ / BM);
    gemm_h<0><<<go, thr, GEMM_SMEM>>>(Ph, Vth, O, nullptr, SEQ, OUTD, 1.0f);
}

// round 12
// speedup vs baseline: 1.0022x; 1.0022x over previous
#include <cuda_runtime.h>
#include <cuda_fp16.h>
#include <stdint.h>
#include <stddef.h>
#include <math.h>

#define SEQ 4096
#define EMB 1024
#define OUTD 1024

// ---------------- scratch (__device__ globals; allocation-free rule) -------
__device__ __half g_Xh[(size_t)SEQ * EMB];
__device__ __half g_WQh[(size_t)OUTD * EMB];
__device__ __half g_WKh[(size_t)OUTD * EMB];
__device__ __half g_WVh[(size_t)OUTD * EMB];
__device__ __half g_Qh[(size_t)SEQ * OUTD];
__device__ __half g_Kh[(size_t)SEQ * OUTD];
__device__ __half g_Vth[(size_t)OUTD * SEQ];          // V^T
__device__ float  g_S[(size_t)SEQ * SEQ];
__device__ __half g_Ph[(size_t)SEQ * SEQ];

// ---------------- PTX helpers ----------------------------------------------
__device__ __forceinline__ uint32_t smem_u32(const void* p) {
    uint32_t a;
    asm("{ .reg .u64 t; cvta.to.shared.u64 t, %1; cvt.u32.u64 %0, t; }"
        : "=r"(a) : "l"(p));
    return a;
}
__device__ __forceinline__ void cp16(uint32_t dst, const void* src) {
    asm volatile("cp.async.cg.shared.global [%0], [%1], 16;" :: "r"(dst), "l"(src));
}
__device__ __forceinline__ void cp_commit() {
    asm volatile("cp.async.commit_group;" ::: "memory");
}
__device__ __forceinline__ void cp_wait2() {
    asm volatile("cp.async.wait_group 2;" ::: "memory");
}
__device__ __forceinline__ void ldsm4(uint32_t& r0, uint32_t& r1, uint32_t& r2,
                                      uint32_t& r3, uint32_t addr) {
    asm volatile("ldmatrix.sync.aligned.m8n8.x4.shared.b16 {%0,%1,%2,%3}, [%4];"
                 : "=r"(r0), "=r"(r1), "=r"(r2), "=r"(r3) : "r"(addr));
}
__device__ __forceinline__ void mma16816(float* c, const uint32_t* a,
                                         const uint32_t* b) {
    asm volatile(
        "mma.sync.aligned.m16n8k16.row.col.f32.f16.f16.f32 "
        "{%0,%1,%2,%3}, {%4,%5,%6,%7}, {%8,%9}, {%0,%1,%2,%3};"
        : "+f"(c[0]), "+f"(c[1]), "+f"(c[2]), "+f"(c[3])
        : "r"(a[0]), "r"(a[1]), "r"(a[2]), "r"(a[3]), "r"(b[0]), "r"(b[1]));
}

// ---------------- plain fp16 warp-MMA GEMM ---------------------------------
// C[M,N] = alpha * A[M,K] @ B[N,K]^T, fp16 A and B, K-major rows.
// CTA 256x128, BK=64, 3 cp.async stages, 16 warps (4M x 4N), warp tile 64x32.
// MODE 0: fp32 C. MODE 1: fp16 C1. MODE 2: fp16 transposed (C*[col][row]).
#define BM 256
#define BN 128
#define BK 64
#define NTHR 512

#define OFF_A 0u
#define OFF_B 32768u
#define STG   49152u
#define GEMM_SMEM (3 * 49152)

template <int MODE>
__global__ void __launch_bounds__(NTHR, 1) gemm_h(
    const __half* __restrict__ A, const __half* __restrict__ B,
    float* __restrict__ Cf, __half* __restrict__ C1,
    int K, int ldc, float alpha)
{
    extern __shared__ char smem_raw[];
    const uint32_t SBASE = smem_u32(smem_raw);

    const int t    = threadIdx.x;
    const int w    = t >> 5;
    const int lane = t & 31;
    const int m0   = blockIdx.y * BM;
    const int n0   = blockIdx.x * BN;
    const int warp_m = (w >> 2) * 64;   // 0..192
    const int warp_n = (w & 3) * 32;    // 0..96

    float acc[4][4][4];
#pragma unroll
    for (int i = 0; i < 4; i++)
#pragma unroll
        for (int j = 0; j < 4; j++)
#pragma unroll
            for (int q = 0; q < 4; q++) acc[i][j][q] = 0.0f;

    // ---- cp.async plan: 6 x 16B chunks per thread per stage ----
    const int trow = t >> 3;             // 0..63
    const int tc8  = t & 7;              // 0..7
    const uint32_t swc = (uint32_t)tc8 * 16;
    const __half* pA = A + (size_t)m0 * K;
    const __half* pB = B + (size_t)n0 * K;

    auto load_stage = [&](int s, int k0) {
        const uint32_t sb = SBASE + (uint32_t)s * STG;
#pragma unroll
        for (int i = 0; i < 6; i++) {
            const bool isA = (i < 4);
            const int row0 = isA ? i * 64 : (i - 4) * 64;
            const __half* base = isA ? pA : pB;
            const uint32_t toff = isA ? OFF_A : OFF_B;
            int rl = row0 + trow;
            const __half* src = base + (size_t)rl * K + tc8 * 8 + k0;
            uint32_t off = toff + (uint32_t)rl * 128 +
                           (swc ^ (((uint32_t)rl & 7) << 4));
            cp16(sb + off, src);
        }
    };

    // ---- ldmatrix address precompute ----
    uint32_t a_off[4], a_xor[4];
#pragma unroll
    for (int mf = 0; mf < 4; mf++) {
        int rl = warp_m + mf * 16 + (lane & 15);
        a_off[mf] = (uint32_t)rl * 128;
        a_xor[mf] = ((uint32_t)rl & 7) << 4;
    }
    const uint32_t a_bc = ((uint32_t)lane >> 4) * 16;
    uint32_t b_off[2], b_xor[2];
#pragma unroll
    for (int nfp = 0; nfp < 2; nfp++) {
        int rl = warp_n + nfp * 16 + (lane & 7) + ((lane & 16) ? 8 : 0);
        b_off[nfp] = (uint32_t)rl * 128;
        b_xor[nfp] = ((uint32_t)rl & 7) << 4;
    }
    const uint32_t b_bc = (((uint32_t)lane >> 3) & 1) * 16;

    const int kt = K / BK;

    // prologue: stages 0,1
    load_stage(0, 0);   cp_commit();
    load_stage(1, BK);  cp_commit();

    for (int it = 0; it < kt; it++) {
        if (it + 2 < kt) load_stage((it + 2) % 3, (it + 2) * BK);
        cp_commit();                       // always (possibly empty group)
        cp_wait2();                        // stage `it` resident
        __syncthreads();

        const uint32_t sb = SBASE + (uint32_t)(it % 3) * STG;

#pragma unroll
        for (int ks = 0; ks < 4; ks++) {
            const uint32_t bcA = (uint32_t)ks * 32 + a_bc;
            const uint32_t bcB = (uint32_t)ks * 32 + b_bc;
            uint32_t bh[4][2];
#pragma unroll
            for (int nfp = 0; nfp < 2; nfp++) {
                uint32_t r0, r1, r2, r3;
                ldsm4(r0, r1, r2, r3, sb + OFF_B + b_off[nfp] + (bcB ^ b_xor[nfp]));
                bh[2 * nfp][0] = r0; bh[2 * nfp][1] = r1;
                bh[2 * nfp + 1][0] = r2; bh[2 * nfp + 1][1] = r3;
            }
#pragma unroll
            for (int mf = 0; mf < 4; mf++) {
                uint32_t ah[4];
                ldsm4(ah[0], ah[1], ah[2], ah[3],
                      sb + OFF_A + a_off[mf] + (bcA ^ a_xor[mf]));
#pragma unroll
                for (int nf = 0; nf < 4; nf++)
                    mma16816(acc[mf][nf], ah, bh[nf]);
            }
        }
        __syncthreads();
    }

    // ---- epilogue ----
#pragma unroll
    for (int mf = 0; mf < 4; mf++) {
#pragma unroll
        for (int nf = 0; nf < 4; nf++) {
            int row = m0 + warp_m + mf * 16 + (lane >> 2);
            int col = n0 + warp_n + nf * 8 + (lane & 3) * 2;
            float f00 = acc[mf][nf][0] * alpha;
            float f01 = acc[mf][nf][1] * alpha;
            float f10 = acc[mf][nf][2] * alpha;
            float f11 = acc[mf][nf][3] * alpha;
            if (MODE == 0) {
                *(float2*)(Cf + (size_t)row * ldc + col)       = make_float2(f00, f01);
                *(float2*)(Cf + (size_t)(row + 8) * ldc + col) = make_float2(f10, f11);
            } else if (MODE == 1) {
                *(__half2*)(C1 + (size_t)row * ldc + col) =
                    __halves2half2(__float2half_rn(f00), __float2half_rn(f01));
                *(__half2*)(C1 + (size_t)(row + 8) * ldc + col) =
                    __halves2half2(__float2half_rn(f10), __float2half_rn(f11));
            } else { // MODE 2: transposed single: C*[col][row], ldc = M_total
                C1[(size_t)col * ldc + row]           = __float2half_rn(f00);
                C1[(size_t)(col + 1) * ldc + row]     = __float2half_rn(f01);
                C1[(size_t)col * ldc + row + 8]       = __float2half_rn(f10);
                C1[(size_t)(col + 1) * ldc + row + 8] = __float2half_rn(f11);
            }
        }
    }
}

// ---------------- fp32 -> fp16 convert --------------------------------------
__global__ void __launch_bounds__(256) conv_half_kernel(
    const float* __restrict__ in, __half* __restrict__ out, int n4)
{
    int i = blockIdx.x * 256 + threadIdx.x;
    if (i >= n4) return;
    float4 v = ((const float4*)in)[i];
    ((__half2*)out)[2 * i]     = __halves2half2(__float2half_rn(v.x), __float2half_rn(v.y));
    ((__half2*)out)[2 * i + 1] = __halves2half2(__float2half_rn(v.z), __float2half_rn(v.w));
}

// ---------------- row softmax -> fp16 Ph ------------------------------------
__global__ void __launch_bounds__(256) softmax_h_kernel(
    const float* __restrict__ S, __half* __restrict__ Ph)
{
    __shared__ float red[8];
    const int row = blockIdx.x;
    const int t   = threadIdx.x;
    const float* p = S + (size_t)row * SEQ;

    float4 v[4];
#pragma unroll
    for (int i = 0; i < 4; i++)
        v[i] = *(const float4*)(p + 4 * (t + 256 * i));

    float mx = -INFINITY;
#pragma unroll
    for (int i = 0; i < 4; i++)
        mx = fmaxf(mx, fmaxf(fmaxf(v[i].x, v[i].y), fmaxf(v[i].z, v[i].w)));
#pragma unroll
    for (int o = 16; o > 0; o >>= 1)
        mx = fmaxf(mx, __shfl_xor_sync(0xFFFFFFFFu, mx, o));
    if ((t & 31) == 0) red[t >> 5] = mx;
    __syncthreads();
    {
        float m = red[t & 7];
#pragma unroll
        for (int o = 4; o > 0; o >>= 1)
            m = fmaxf(m, __shfl_xor_sync(0xFFFFFFFFu, m, o));
        mx = m;
    }
    __syncthreads();

    float sum = 0.0f;
#pragma unroll
    for (int i = 0; i < 4; i++) {
        v[i].x = expf(v[i].x - mx); v[i].y = expf(v[i].y - mx);
        v[i].z = expf(v[i].z - mx); v[i].w = expf(v[i].w - mx);
        sum += v[i].x + v[i].y + v[i].z + v[i].w;
    }
#pragma unroll
    for (int o = 16; o > 0; o >>= 1)
        sum += __shfl_xor_sync(0xFFFFFFFFu, sum, o);
    if ((t & 31) == 0) red[t >> 5] = sum;
    __syncthreads();
    {
        float s2 = red[t & 7];
#pragma unroll
        for (int o = 4; o > 0; o >>= 1)
            s2 += __shfl_xor_sync(0xFFFFFFFFu, s2, o);
        sum = s2;
    }

    const float inv = 1.0f / sum;
#pragma unroll
    for (int i = 0; i < 4; i++) {
        size_t idx = (size_t)row * SEQ + 4 * (t + 256 * i);
        *(__half2*)(Ph + idx) = __halves2half2(
            __float2half_rn(v[i].x * inv), __float2half_rn(v[i].y * inv));
        *(__half2*)(Ph + idx + 2) = __halves2half2(
            __float2half_rn(v[i].z * inv), __float2half_rn(v[i].w * inv));
    }
}

// ---------------------------------------------------------------------------
extern "C" void kernel_launch(void* const* d_in, const int* in_sizes, int n_in,
                              void* d_out, int out_size)
{
    (void)in_sizes; (void)n_in; (void)out_size;
    const float* X  = (const float*)d_in[0];
    const float* WQ = (const float*)d_in[1];
    const float* WK = (const float*)d_in[2];
    const float* WV = (const float*)d_in[3];
    float* O = (float*)d_out;

    __half *Xh, *WQh, *WKh, *WVh, *Qh, *Kh, *Vth, *Ph;
    float* S;
    cudaGetSymbolAddress((void**)&Xh, g_Xh);
    cudaGetSymbolAddress((void**)&WQh, g_WQh);
    cudaGetSymbolAddress((void**)&WKh, g_WKh);
    cudaGetSymbolAddress((void**)&WVh, g_WVh);
    cudaGetSymbolAddress((void**)&Qh, g_Qh);
    cudaGetSymbolAddress((void**)&Kh, g_Kh);
    cudaGetSymbolAddress((void**)&Vth, g_Vth);
    cudaGetSymbolAddress((void**)&Ph, g_Ph);
    cudaGetSymbolAddress((void**)&S, g_S);

    cudaFuncSetAttribute(gemm_h<0>, cudaFuncAttributeMaxDynamicSharedMemorySize, GEMM_SMEM);
    cudaFuncSetAttribute(gemm_h<1>, cudaFuncAttributeMaxDynamicSharedMemorySize, GEMM_SMEM);
    cudaFuncSetAttribute(gemm_h<2>, cudaFuncAttributeMaxDynamicSharedMemorySize, GEMM_SMEM);

    // 1) fp32 -> fp16 conversions
    {
        int n4 = SEQ * EMB / 4;
        conv_half_kernel<<<(n4 + 255) / 256, 256>>>(X, Xh, n4);
        int w4 = OUTD * EMB / 4;
        conv_half_kernel<<<(w4 + 255) / 256, 256>>>(WQ, WQh, w4);
        conv_half_kernel<<<(w4 + 255) / 256, 256>>>(WK, WKh, w4);
        conv_half_kernel<<<(w4 + 255) / 256, 256>>>(WV, WVh, w4);
    }

    dim3 thr(NTHR);

    // 2) projections (NT): Q, K fp16; V fp16 transposed
    dim3 gp(OUTD / BN, SEQ / BM);
    gemm_h<1><<<gp, thr, GEMM_SMEM>>>(Xh, WQh, nullptr, Qh, EMB, OUTD, 1.0f);
    gemm_h<1><<<gp, thr, GEMM_SMEM>>>(Xh, WKh, nullptr, Kh, EMB, OUTD, 1.0f);
    gemm_h<2><<<gp, thr, GEMM_SMEM>>>(Xh, WVh, nullptr, Vth, EMB, SEQ, 1.0f);

    // 3) scores: S = (Q @ K^T) / 32
    dim3 gs(SEQ / BN, SEQ / BM);
    gemm_h<0><<<gs, thr, GEMM_SMEM>>>(Qh, Kh, S, nullptr, OUTD, SEQ, 0.03125f);

    // 4) softmax -> fp16 Ph
    softmax_h_kernel<<<SEQ, 256>>>(S, Ph);

    // 5) O = P @ V (B = V^T)
    dim3 go(OUTD / BN, SEQ / BM);
    gemm_h<0><<<go, thr, GEMM_SMEM>>>(Ph, Vth, O, nullptr, SEQ, OUTD, 1.0f);
}